// round 17
// baseline (speedup 1.0000x reference)
#include <cuda_runtime.h>
#include <cuda_fp16.h>
#include <cstdint>

#define HH 128
#define WW 128
#define HW 16384
#define NN 65536
#define HID 128
#define NL 6
#define NPRM 5
#define EPSV 1e-5f
#define DTV 0.1f
#define NCH 3
#define NBATCH 4
#define PS 68  // uint32 (half2) words per plane row (row stride 272B)
#define SBUF 1024
#define WTHALVES 17408  // 128 rows * 136 halves per transposed weight plane

__device__ __half g_fh[(size_t)NN * HID];
__device__ __half g_Ah[(size_t)NN * HID];
__device__ __half g_Bh[(size_t)NN * HID];
__device__ float g_tmp[(size_t)NN * HID];
__device__ float g_stats[2 * SBUF];
__device__ __half g_wth[(size_t)36 * WTHALVES];  // 6 layers x 6 matrices

__constant__ int c_dr[8] = {-1, -1, -1, 0, 0, 1, 1, 1};
__constant__ int c_dc[8] = {-1, 0, 1, -1, 1, -1, 0, 1};

__device__ __forceinline__ float swishf(float x) {
    return __fdividef(x, 1.0f + __expf(-x));
}
__device__ __forceinline__ __half2 u2h(uint32_t u) {
    return *reinterpret_cast<__half2*>(&u);
}
__device__ __forceinline__ uint32_t h2u(__half2 h) {
    return *reinterpret_cast<uint32_t*>(&h);
}
__device__ __forceinline__ __half2 tanh2(__half2 x) {
    uint32_t r;
    asm("tanh.approx.f16x2 %0, %1;" : "=r"(r) : "r"(h2u(x)));
    return u2h(r);
}
// half2 swish: x*sigmoid(x) = h + h*tanh(h), h = x/2
__device__ __forceinline__ __half2 psw2(__half2 x) {
    __half2 h = __hmul2(x, __float2half2_rn(0.5f));
    __half2 t = tanh2(h);
    return __hfma2(h, t, h);
}

// ---- one-time weight transpose: W[k][n] fp32 -> Wt[n][k] fp16 (global) ----
__global__ void k_prep(const float* __restrict__ msg1W,
                       const float* __restrict__ msg2W,
                       const float* __restrict__ upd1W,
                       const float* __restrict__ upd2W) {
    int m_idx = blockIdx.x, l = m_idx / 6, m = m_idx % 6;
    const float* W;
    switch (m) {
        case 0: W = msg1W + (size_t)l * 264 * 128; break;              // msg1 W_t
        case 1: W = msg1W + (size_t)l * 264 * 128 + 128 * 128; break;  // msg1 W_s
        case 2: W = msg2W + (size_t)l * 16384; break;                  // msg2
        case 3: W = upd1W + (size_t)l * 261 * 128 + 128 * 128; break;  // U1 agg
        case 4: W = upd1W + (size_t)l * 261 * 128; break;              // U1 f
        default: W = upd2W + (size_t)l * 16384; break;                 // U2
    }
    __half* H = g_wth + (size_t)m_idx * WTHALVES;
    for (int i = threadIdx.x; i < 16384; i += 256) {
        int n = i & 127, k = i >> 7;
        H[n * 136 + k] = __float2half_rn(W[k * 128 + n]);
    }
}
__device__ __forceinline__ void copy_wt(uint32_t* Hw, int mat, int tid) {
    const uint4* s = (const uint4*)(g_wth + (size_t)mat * WTHALVES);
    uint4* d = (uint4*)Hw;
    for (int i = tid; i < 2176; i += 256) d[i] = s[i];
}

// ---------------- fp16 GEMMs (m16n8k16) with ldmatrix ----------------
__device__ __forceinline__ void hmma16(uint32_t* d, uint32_t a0, uint32_t a1,
                                       uint32_t a2, uint32_t a3, uint32_t b0,
                                       uint32_t b1) {
    asm volatile(
        "mma.sync.aligned.m16n8k16.row.col.f16.f16.f16.f16 "
        "{%0,%1},{%2,%3,%4,%5},{%6,%7},{%0,%1};"
        : "+r"(d[0]), "+r"(d[1])
        : "r"(a0), "r"(a1), "r"(a2), "r"(a3), "r"(b0), "r"(b1));
}
__device__ __forceinline__ void ldsm4(uint32_t* r, uint32_t addr) {
    asm volatile("ldmatrix.sync.aligned.m8n8.x4.shared.b16 {%0,%1,%2,%3}, [%4];"
                 : "=r"(r[0]), "=r"(r[1]), "=r"(r[2]), "=r"(r[3]) : "r"(addr));
}
__device__ __forceinline__ void ldsm2(uint32_t* r, uint32_t addr) {
    asm volatile("ldmatrix.sync.aligned.m8n8.x2.shared.b16 {%0,%1}, [%2];"
                 : "=r"(r[0]), "=r"(r[1]) : "r"(addr));
}
#define ZERO442(a)                                                     \
    _Pragma("unroll") for (int _i = 0; _i < 4; ++_i)                   \
        _Pragma("unroll") for (int _j = 0; _j < 4; ++_j)               \
            _Pragma("unroll") for (int _q = 0; _q < 2; ++_q) a[_i][_j][_q] = 0u;

// f16-acc GEMM: D[64x32] per warp
__device__ __forceinline__ void gemmh16(const uint32_t* __restrict__ Ah,
                                        const uint32_t* __restrict__ Bh,
                                        uint32_t accd[4][4][2], int m0, int n0c,
                                        int lane) {
    uint32_t abase = (uint32_t)__cvta_generic_to_shared(Ah) +
                     (uint32_t)(m0 + (lane & 15)) * 272 + ((lane >> 4) & 1) * 16;
    uint32_t bbase = (uint32_t)__cvta_generic_to_shared(Bh) +
                     (uint32_t)(n0c + (lane & 7)) * 272 + ((lane >> 3) & 1) * 16;
#pragma unroll 2
    for (int s = 0; s < 8; ++s) {
        uint32_t bh[4][2];
#pragma unroll
        for (int nj = 0; nj < 4; ++nj)
            ldsm2(bh[nj], bbase + nj * (8 * 272) + s * 32);
#pragma unroll
        for (int mi = 0; mi < 4; ++mi) {
            uint32_t a[4];
            ldsm4(a, abase + mi * (16 * 272) + s * 32);
#pragma unroll
            for (int nj = 0; nj < 4; ++nj)
                hmma16(accd[mi][nj], a[0], a[1], a[2], a[3], bh[nj][0], bh[nj][1]);
        }
    }
}

// ------ k_msgA_mm: (fused prev-layer norm) + A = f@W_t + pc, Bm = f@W_s ------
__global__ __launch_bounds__(256, 3) void k_msgA_mm(
    const float* __restrict__ cp, const float* __restrict__ msg1W,
    const float* __restrict__ msg1b, int l) {
    extern __shared__ char smem[];
    uint32_t* Fh = (uint32_t*)smem;             // 34816
    uint32_t* Wh = (uint32_t*)(smem + 34816);   // 34816
    uint32_t* pc2_s = (uint32_t*)(smem + 69632); // 256
    float* mean_s = (float*)(smem + 70144);     // 512
    float* rstd_s = (float*)(smem + 70656);     // 512 -> 71168

    const int tid = threadIdx.x, warp = tid >> 5, lane = tid & 31;
    const int g = lane >> 2, t = lane & 3;
    const int m0 = (warp >> 2) * 64, n0c = (warp & 3) * 32;
    const int nb0 = blockIdx.x << 7, b = nb0 >> 14;
    const float* Wl1 = msg1W + (size_t)l * 264 * 128;

    if (blockIdx.x == 0)
        for (int i = tid; i < SBUF; i += 256) g_stats[(l & 1) * SBUF + i] = 0.0f;
    if (tid < 64) {
        float s0 = msg1b[l * 128 + 2 * tid], s1 = msg1b[l * 128 + 2 * tid + 1];
#pragma unroll
        for (int p = 0; p < NPRM; ++p) {
            float cpv = cp[b * NPRM + p];
            s0 = fmaf(cpv, Wl1[(259 + p) * 128 + 2 * tid], s0);
            s1 = fmaf(cpv, Wl1[(259 + p) * 128 + 2 * tid + 1], s1);
        }
        pc2_s[tid] = h2u(__floats2half2_rn(s0, s1));
    }
    if (l > 0) {  // fused layernorm of previous layer's g_tmp; g_fh out
        if (tid < 128) {
            const float* st = g_stats + ((l - 1) & 1) * SBUF + b * 256;
            float m = st[tid] * (1.0f / (float)HW);
            float v = st[128 + tid] * (1.0f / (float)HW) - m * m;
            mean_s[tid] = m;
            rstd_s[tid] = rsqrtf(v + EPSV);
        }
        __syncthreads();
#pragma unroll 4
        for (int i = tid; i < 4096; i += 256) {
            int c = i >> 5, q = i & 31, j = q * 4;
            float4 v = *(const float4*)(g_tmp + (size_t)(nb0 + c) * 128 + j);
            v.x = (v.x - mean_s[j + 0]) * rstd_s[j + 0];
            v.y = (v.y - mean_s[j + 1]) * rstd_s[j + 1];
            v.z = (v.z - mean_s[j + 2]) * rstd_s[j + 2];
            v.w = (v.w - mean_s[j + 3]) * rstd_s[j + 3];
            uint2 hp = make_uint2(h2u(__floats2half2_rn(v.x, v.y)),
                                  h2u(__floats2half2_rn(v.z, v.w)));
            *(uint2*)(g_fh + (size_t)(nb0 + c) * 128 + j) = hp;  // edge reads this
            *(uint2*)(Fh + c * PS + 2 * q) = hp;
        }
    } else {
#pragma unroll 4
        for (int i = tid; i < 4096; i += 256) {
            int c = i >> 5, q = i & 31;
            *(uint2*)(Fh + c * PS + 2 * q) =
                *(const uint2*)(g_fh + (size_t)(nb0 + c) * 128 + q * 4);
        }
    }
    copy_wt(Wh, l * 6 + 0, tid);  // W_t
    __syncthreads();

    uint32_t accd[4][4][2];
    ZERO442(accd);
    gemmh16(Fh, Wh, accd, m0, n0c, lane);
#pragma unroll
    for (int mi = 0; mi < 4; ++mi) {
        int c0 = m0 + 16 * mi + g;
#pragma unroll
        for (int nj = 0; nj < 4; ++nj) {
            int col = n0c + 8 * nj + 2 * t;
            __half2 pc = u2h(pc2_s[col >> 1]);
            *(uint32_t*)(g_Ah + (size_t)(nb0 + c0) * 128 + col) =
                h2u(__hadd2(u2h(accd[mi][nj][0]), pc));
            *(uint32_t*)(g_Ah + (size_t)(nb0 + c0 + 8) * 128 + col) =
                h2u(__hadd2(u2h(accd[mi][nj][1]), pc));
        }
    }
    __syncthreads();
    copy_wt(Wh, l * 6 + 1, tid);  // W_s
    __syncthreads();
    ZERO442(accd);
    gemmh16(Fh, Wh, accd, m0, n0c, lane);
#pragma unroll
    for (int mi = 0; mi < 4; ++mi) {
        int c0 = m0 + 16 * mi + g;
#pragma unroll
        for (int nj = 0; nj < 4; ++nj) {
            int col = n0c + 8 * nj + 2 * t;
            *(uint32_t*)(g_Bh + (size_t)(nb0 + c0) * 128 + col) = accd[mi][nj][0];
            *(uint32_t*)(g_Bh + (size_t)(nb0 + c0 + 8) * 128 + col) = accd[mi][nj][1];
        }
    }
}

// ------------- k_edge_mm: messages + agg + update MLP -------------
__global__ __launch_bounds__(256, 2) void k_edge_mm(
    const float* __restrict__ inp, const float* __restrict__ cp,
    const float* __restrict__ msg1W, const float* __restrict__ msg2b,
    const float* __restrict__ upd1W, const float* __restrict__ upd1b,
    const float* __restrict__ upd2b, int l) {
    extern __shared__ char smem[];
    uint32_t* Mh0 = (uint32_t*)smem;              // 34816
    uint32_t* Mh1 = (uint32_t*)(smem + 34816);    // 34816
    uint32_t* Wh = (uint32_t*)(smem + 69632);     // 34816
    uint32_t* posW2 = (uint32_t*)(smem + 104448); // 2048
    uint32_t* wu2 = (uint32_t*)(smem + 106496);   // 256
    uint32_t* b2m2 = (uint32_t*)(smem + 106752);  // 256
    uint32_t* pc2u = (uint32_t*)(smem + 107264);  // 256
    uint32_t* b2u2 = (uint32_t*)(smem + 107520);  // 256
    uint32_t* du2a = (uint32_t*)(smem + 108288);  // 4096
    float* cp_s = (float*)(smem + 112384);        // 32 -> 112416
    float* stage = (float*)smem;                  // late reuse (67584 < Mh0+Mh1)

    const int tid = threadIdx.x, warp = tid >> 5, lane = tid & 31;
    const int g = lane >> 2, t = lane & 3;
    const int m0 = (warp >> 2) * 64, n0c = (warp & 3) * 32;
    const int gr = blockIdx.x, b = gr >> 7, r = gr & 127, nb0 = gr << 7;
    const float* W1l = msg1W + (size_t)l * 264 * 128;
    const float* U1 = upd1W + (size_t)l * 261 * 128;
    const int qq = tid & 31, crow = tid >> 5;

    if (tid < 8) cp_s[tid] = (tid < NPRM) ? cp[b * NPRM + tid] : 0.0f;
    if (tid < 64) {
        b2m2[tid] = h2u(__floats2half2_rn(msg2b[l * 128 + 2 * tid],
                                          msg2b[l * 128 + 2 * tid + 1]));
        wu2[tid] = h2u(__floats2half2_rn(W1l[256 * 128 + 2 * tid],
                                         W1l[256 * 128 + 2 * tid + 1]));
        b2u2[tid] = h2u(__floats2half2_rn(upd2b[l * 128 + 2 * tid],
                                          upd2b[l * 128 + 2 * tid + 1]));
    }
    __syncthreads();
    if (tid < 64) {  // pcu as half2 (needs cp_s)
        float s0 = upd1b[l * 128 + 2 * tid], s1 = upd1b[l * 128 + 2 * tid + 1];
#pragma unroll
        for (int p = 0; p < NPRM; ++p) {
            s0 = fmaf(cp_s[p], U1[(256 + p) * 128 + 2 * tid], s0);
            s1 = fmaf(cp_s[p], U1[(256 + p) * 128 + 2 * tid + 1], s1);
        }
        pc2u[tid] = h2u(__floats2half2_rn(s0, s1));
    }
    for (int i = tid; i < 512; i += 256) {  // posW half2: [d][64]
        int d = i >> 6, j = i & 63;
        float pdx = (float)(-c_dr[d]) * (1.0f / 127.0f) * cp_s[1];
        float pdy = (float)(-c_dc[d]) * (1.0f / 127.0f) * cp_s[0];
        float v0 = pdx * W1l[257 * 128 + 2 * j] + pdy * W1l[258 * 128 + 2 * j];
        float v1 = pdx * W1l[257 * 128 + 2 * j + 1] + pdy * W1l[258 * 128 + 2 * j + 1];
        posW2[i] = h2u(__floats2half2_rn(v0, v1));
    }
#pragma unroll 2
    for (int i = tid; i < 1024; i += 256) {  // du for ALL 8 directions upfront
        int d = i >> 7, c = i & 127;
        int n = nb0 + c, nb = n + c_dr[d] * WW + c_dc[d];
        nb = min(max(nb, 0), NN - 1);
        int bb = nb >> 14;
        float du = inp[b * NCH * HW + (n - b * HW)] -
                   inp[bb * NCH * HW + (nb - bb * HW)];
        du2a[i] = h2u(__half2half2(__float2half_rn(du)));
    }
    copy_wt(Wh, l * 6 + 2, tid);  // msg2W

    // register-cache self-A: thread owns q=qq, c = crow + 8k
    uint2 Areg[16];
#pragma unroll
    for (int k = 0; k < 16; ++k)
        Areg[k] = *(const uint2*)(g_Ah + (size_t)(nb0 + crow + 8 * k) * 128 + qq * 4);
    __syncthreads();  // init fills visible

    __half2 agg[4][4][2];
#pragma unroll
    for (int i = 0; i < 4; ++i)
#pragma unroll
        for (int j = 0; j < 4; ++j) {
            agg[i][j][0] = __float2half2_rn(0.0f);
            agg[i][j][1] = __float2half2_rn(0.0f);
        }

    int ad = 0;  // active-direction counter (buffer parity)
#pragma unroll 1
    for (int d = 0; d < 8; ++d) {
        const int dr = c_dr[d], dc = c_dc[d];
        if ((unsigned)(r + dr) >= (unsigned)HH) continue;
        uint32_t* Mb = (ad & 1) ? Mh1 : Mh0;
        // build M into Mb (other buffer may still be read by previous gemm)
#pragma unroll 4
        for (int k = 0; k < 16; ++k) {
            int c = crow + 8 * k;
            int nb = nb0 + c + dr * WW + dc;
            nb = min(max(nb, 0), NN - 1);
            uint2 bm = *(const uint2*)(g_Bh + (size_t)nb * 128 + qq * 4);
            uint2 av = Areg[k];
            __half2 hd = u2h(du2a[d * 128 + c]);
            __half2 s0 = __hadd2(__hadd2(u2h(av.x), u2h(bm.x)),
                                 __hfma2(hd, u2h(wu2[2 * qq]),
                                         u2h(posW2[d * 64 + 2 * qq])));
            __half2 s1 = __hadd2(__hadd2(u2h(av.y), u2h(bm.y)),
                                 __hfma2(hd, u2h(wu2[2 * qq + 1]),
                                         u2h(posW2[d * 64 + 2 * qq + 1])));
            *(uint2*)(Mb + c * PS + 2 * qq) = make_uint2(h2u(psw2(s0)), h2u(psw2(s1)));
        }
        __syncthreads();  // Mb visible; also proves gemm(ad-1) done by all
        uint32_t accd[4][4][2];
        ZERO442(accd);
        gemmh16(Mb, Wh, accd, m0, n0c, lane);
#pragma unroll
        for (int mi = 0; mi < 4; ++mi) {
            int c0 = m0 + 16 * mi + g;
            bool ok0 = (unsigned)(c0 + dc) < (unsigned)WW;
            bool ok1 = (unsigned)(c0 + 8 + dc) < (unsigned)WW;
#pragma unroll
            for (int nj = 0; nj < 4; ++nj) {
                int col = n0c + 8 * nj + 2 * t;
                __half2 bb = u2h(b2m2[col >> 1]);
                if (ok0)
                    agg[mi][nj][0] = __hadd2(
                        agg[mi][nj][0], psw2(__hadd2(u2h(accd[mi][nj][0]), bb)));
                if (ok1)
                    agg[mi][nj][1] = __hadd2(
                        agg[mi][nj][1], psw2(__hadd2(u2h(accd[mi][nj][1]), bb)));
            }
        }
        ++ad;
    }
    __syncthreads();  // all message gemms done; Mh0/Mh1/Wh free

    // -------- update MLP (all f16 accumulators) --------
    {   // agg -> Mh0
        int crn = 1 + (r > 0) + (r < HH - 1);
#pragma unroll
        for (int mi = 0; mi < 4; ++mi) {
#pragma unroll
            for (int hh = 0; hh < 2; ++hh) {
                int c0 = m0 + 16 * mi + g + 8 * hh;
                float inv = 1.0f / (float)(crn * (1 + (c0 > 0) + (c0 < WW - 1)) - 1);
                __half2 inv2 = __float2half2_rn(inv);
#pragma unroll
                for (int nj = 0; nj < 4; ++nj)
                    Mh0[c0 * PS + (n0c >> 1) + 4 * nj + t] =
                        h2u(__hmul2(agg[mi][nj][hh], inv2));
            }
        }
    }
#pragma unroll 4
    for (int k = 0; k < 16; ++k) {  // f -> Mh1 (pure fp16 copy)
        int c = crow + 8 * k;
        *(uint2*)(Mh1 + c * PS + 2 * qq) =
            *(const uint2*)(g_fh + (size_t)(nb0 + c) * 128 + qq * 4);
    }
    copy_wt(Wh, l * 6 + 3, tid);  // U1 agg rows
    __syncthreads();
    uint32_t acc2d[4][4][2];
    ZERO442(acc2d);
    gemmh16(Mh0, Wh, acc2d, m0, n0c, lane);
    __syncthreads();
    copy_wt(Wh, l * 6 + 4, tid);  // U1 f rows
    __syncthreads();
    gemmh16(Mh1, Wh, acc2d, m0, n0c, lane);  // accumulate
    __syncthreads();
#pragma unroll
    for (int mi = 0; mi < 4; ++mi) {  // h1 = swish(acc2 + pcu) -> Mh0
#pragma unroll
        for (int nj = 0; nj < 4; ++nj) {
            int col = n0c + 8 * nj + 2 * t;
            int c0 = m0 + 16 * mi + g;
            __half2 pc = u2h(pc2u[col >> 1]);
            Mh0[c0 * PS + (col >> 1)] =
                h2u(psw2(__hadd2(u2h(acc2d[mi][nj][0]), pc)));
            Mh0[(c0 + 8) * PS + (col >> 1)] =
                h2u(psw2(__hadd2(u2h(acc2d[mi][nj][1]), pc)));
        }
    }
    copy_wt(Wh, l * 6 + 5, tid);  // U2
    __syncthreads();
    uint32_t acc3d[4][4][2];
    ZERO442(acc3d);
    gemmh16(Mh0, Wh, acc3d, m0, n0c, lane);
    __syncthreads();  // gemm done; stage may overwrite Mh0/Mh1

    // -------- residual + stores + layernorm stats --------
#pragma unroll
    for (int mi = 0; mi < 4; ++mi) {
#pragma unroll
        for (int half = 0; half < 2; ++half) {
            int c0 = m0 + 16 * mi + g + 8 * half;
#pragma unroll
            for (int nj = 0; nj < 4; ++nj) {
                int col = n0c + 8 * nj + 2 * t;
                __half2 fh = u2h(*(const uint32_t*)(g_fh + (size_t)(nb0 + c0) * 128 + col));
                __half2 upd = psw2(__hadd2(u2h(acc3d[mi][nj][half]),
                                           u2h(b2u2[col >> 1])));
                float v0 = __low2float(fh) + __low2float(upd);
                float v1 = __high2float(fh) + __high2float(upd);
                *(float2*)(g_tmp + (size_t)(nb0 + c0) * 128 + col) = make_float2(v0, v1);
                *(float2*)(stage + c0 * 132 + col) = make_float2(v0, v1);
            }
        }
    }
    __syncthreads();
    if (tid < 128) {
        float S = 0.0f, S2 = 0.0f;
#pragma unroll 4
        for (int gg = 0; gg < 128; ++gg) {
            float v = stage[gg * 132 + tid];
            S += v;
            S2 += v * v;
        }
        atomicAdd(&g_stats[(l & 1) * SBUF + b * 256 + tid], S);
        atomicAdd(&g_stats[(l & 1) * SBUF + b * 256 + 128 + tid], S2);
    }
}

// ================= fp32 kernels =================
#define ACC_ZERO(acc)                                                  \
    _Pragma("unroll") for (int _i = 0; _i < 4; ++_i)                   \
        _Pragma("unroll") for (int _j = 0; _j < 8; ++_j) acc[_i][_j] = 0.0f;

template <int RSTEP>
__device__ __forceinline__ void gemm128(const float* __restrict__ As, int lda,
                                        const float* __restrict__ Ws, int ldw,
                                        float acc[4][8], int tr, int tc) {
#pragma unroll 4
    for (int k4 = 0; k4 < 32; ++k4) {
        float4 a[4];
#pragma unroll
        for (int i = 0; i < 4; ++i)
            a[i] = *(const float4*)(As + (tr + i * RSTEP) * lda + k4 * 4);
        const float* wp = Ws + (k4 * 4) * ldw + tc * 8;
#pragma unroll
        for (int kk = 0; kk < 4; ++kk) {
            float4 b0 = *(const float4*)(wp + kk * ldw);
            float4 b1 = *(const float4*)(wp + kk * ldw + 4);
#pragma unroll
            for (int i = 0; i < 4; ++i) {
                float av = ((const float*)(a + i))[kk];
                acc[i][0] = fmaf(av, b0.x, acc[i][0]);
                acc[i][1] = fmaf(av, b0.y, acc[i][1]);
                acc[i][2] = fmaf(av, b0.z, acc[i][2]);
                acc[i][3] = fmaf(av, b0.w, acc[i][3]);
                acc[i][4] = fmaf(av, b1.x, acc[i][4]);
                acc[i][5] = fmaf(av, b1.y, acc[i][5]);
                acc[i][6] = fmaf(av, b1.z, acc[i][6]);
                acc[i][7] = fmaf(av, b1.w, acc[i][7]);
            }
        }
    }
}

__global__ __launch_bounds__(256, 2) void k_embed(
    const float* __restrict__ inp, const float* __restrict__ cp,
    const float* __restrict__ W1, const float* __restrict__ b1,
    const float* __restrict__ W2, const float* __restrict__ b2) {
    extern __shared__ float sm[];
    float* e_s = sm;
    float* W1_s = e_s + 64 * 8;
    float* b1_s = W1_s + 8 * 128;
    float* h1_s = b1_s + 128;
    float* W2_s = h1_s + 64 * 132;
    float* b2_s = W2_s + 128 * 128;
    int tid = threadIdx.x;
    int n0 = blockIdx.x * 64, b = n0 / HW;
    for (int i = tid; i < 8 * 128; i += 256) W1_s[i] = W1[i];
    if (tid < 128) { b1_s[tid] = b1[tid]; b2_s[tid] = b2[tid]; }
    for (int i = tid; i < 128 * 32; i += 256)
        ((float4*)W2_s)[i] = ((const float4*)W2)[i];
    if (tid < 64) {
        int n = n0 + tid, rc = n - b * HW;
        int r = rc >> 7, c = rc & 127;
        e_s[tid * 8 + 0] = inp[b * NCH * HW + rc];
        e_s[tid * 8 + 1] = (float)r * (1.0f / 127.0f) * cp[b * NPRM + 1];
        e_s[tid * 8 + 2] = (float)c * (1.0f / 127.0f) * cp[b * NPRM + 0];
#pragma unroll
        for (int p = 0; p < NPRM; ++p) e_s[tid * 8 + 3 + p] = cp[b * NPRM + p];
    }
    __syncthreads();
    int tc = tid & 15, tr = tid >> 4;
#pragma unroll
    for (int i = 0; i < 4; ++i) {
        int row = tr + 16 * i;
#pragma unroll
        for (int j = 0; j < 8; ++j) {
            float s = b1_s[tc * 8 + j];
#pragma unroll
            for (int k = 0; k < 8; ++k)
                s = fmaf(e_s[row * 8 + k], W1_s[k * 128 + tc * 8 + j], s);
            h1_s[row * 132 + tc * 8 + j] = swishf(s);
        }
    }
    __syncthreads();
    float acc[4][8];
    ACC_ZERO(acc);
    gemm128<16>(h1_s, 132, W2_s, 128, acc, tr, tc);
#pragma unroll
    for (int i = 0; i < 4; ++i) {
        int row = tr + 16 * i;
        float v[8];
#pragma unroll
        for (int j = 0; j < 8; ++j)
            v[j] = swishf(acc[i][j] + b2_s[tc * 8 + j]);
        uint4 hp;
        hp.x = h2u(__floats2half2_rn(v[0], v[1]));
        hp.y = h2u(__floats2half2_rn(v[2], v[3]));
        hp.z = h2u(__floats2half2_rn(v[4], v[5]));
        hp.w = h2u(__floats2half2_rn(v[6], v[7]));
        *(uint4*)(g_fh + (size_t)(n0 + row) * 128 + tc * 8) = hp;
    }
}

// k_out with fused final layernorm (stats buffer (NL-1)&1 = 1)
__global__ __launch_bounds__(256, 2) void k_out(
    const float* __restrict__ inp, const float* __restrict__ W1,
    const float* __restrict__ b1, const float* __restrict__ W2,
    const float* __restrict__ b2, float* __restrict__ out) {
    extern __shared__ float sm[];
    float* f_s = sm;
    float* W1_s = f_s + 128 * 132;
    float* b1_s = W1_s + 128 * 64;
    float* W2_s = b1_s + 64;
    float* red_s = W2_s + 64;
    float* mean_s = red_s + 128 * 8;
    float* rstd_s = mean_s + 128;
    int tid = threadIdx.x;
    int n0 = blockIdx.x * 128, b = n0 / HW;
    if (tid < 128) {
        const float* st = g_stats + ((NL - 1) & 1) * SBUF + b * 256;
        float m = st[tid] * (1.0f / (float)HW);
        float v = st[128 + tid] * (1.0f / (float)HW) - m * m;
        mean_s[tid] = m;
        rstd_s[tid] = rsqrtf(v + EPSV);
    }
    __syncthreads();
    for (int i = tid; i < 128 * 32; i += 256) {
        int c = i >> 5, q = i & 31, j = q * 4;
        float4 v = *(const float4*)(g_tmp + (size_t)(n0 + c) * 128 + j);
        v.x = (v.x - mean_s[j + 0]) * rstd_s[j + 0];
        v.y = (v.y - mean_s[j + 1]) * rstd_s[j + 1];
        v.z = (v.z - mean_s[j + 2]) * rstd_s[j + 2];
        v.w = (v.w - mean_s[j + 3]) * rstd_s[j + 3];
        ((float4*)(f_s + c * 132))[q] = v;
    }
    for (int i = tid; i < 128 * 16; i += 256)
        ((float4*)W1_s)[i] = ((const float4*)W1)[i];
    if (tid < 64) { b1_s[tid] = b1[tid]; W2_s[tid] = W2[tid]; }
    __syncthreads();
    int tc = tid & 7, tr = tid >> 3;
    float acc[4][8];
    ACC_ZERO(acc);
    gemm128<32>(f_s, 132, W1_s, 64, acc, tr, tc);
#pragma unroll
    for (int i = 0; i < 4; ++i) {
        float p = 0.0f;
#pragma unroll
        for (int j = 0; j < 8; ++j)
            p += swishf(acc[i][j] + b1_s[tc * 8 + j]) * W2_s[tc * 8 + j];
        red_s[(tr + 32 * i) * 8 + tc] = p;
    }
    __syncthreads();
    if (tid < 128) {
        float d = b2[0];
#pragma unroll
        for (int t = 0; t < 8; ++t) d += red_s[tid * 8 + t];
        int n = n0 + tid;
        out[n] = inp[b * NCH * HW + (n - b * HW)] + DTV * d;
    }
}

// ---------------- host launcher ----------------
extern "C" void kernel_launch(void* const* d_in, const int* in_sizes, int n_in,
                              void* d_out, int out_size) {
    const float* inp   = (const float*)d_in[0];
    const float* cp    = (const float*)d_in[1];
    const float* embW1 = (const float*)d_in[3];
    const float* embb1 = (const float*)d_in[4];
    const float* embW2 = (const float*)d_in[5];
    const float* embb2 = (const float*)d_in[6];
    const float* msg1W = (const float*)d_in[7];
    const float* msg1b = (const float*)d_in[8];
    const float* msg2W = (const float*)d_in[9];
    const float* msg2b = (const float*)d_in[10];
    const float* upd1W = (const float*)d_in[11];
    const float* upd1b = (const float*)d_in[12];
    const float* upd2W = (const float*)d_in[13];
    const float* upd2b = (const float*)d_in[14];
    const float* outW1 = (const float*)d_in[15];
    const float* outb1 = (const float*)d_in[16];
    const float* outW2 = (const float*)d_in[17];
    const float* outb2 = (const float*)d_in[18];
    float* out = (float*)d_out;

    const size_t smE = (size_t)(64 * 8 + 8 * 128 + 128 + 64 * 132 + 128 * 128 + 128) * 4;
    const size_t smO = (size_t)(128 * 132 + 128 * 64 + 64 + 64 + 128 * 8 + 256) * 4;
    const size_t smMA = 71168;
    const size_t smEG = 112416;

    cudaFuncSetAttribute(k_embed, cudaFuncAttributeMaxDynamicSharedMemorySize, (int)smE);
    cudaFuncSetAttribute(k_out, cudaFuncAttributeMaxDynamicSharedMemorySize, (int)smO);
    cudaFuncSetAttribute(k_msgA_mm, cudaFuncAttributeMaxDynamicSharedMemorySize, (int)smMA);
    cudaFuncSetAttribute(k_edge_mm, cudaFuncAttributeMaxDynamicSharedMemorySize, (int)smEG);

    k_prep<<<36, 256>>>(msg1W, msg2W, upd1W, upd2W);
    k_embed<<<NN / 64, 256, smE>>>(inp, cp, embW1, embb1, embW2, embb2);
    for (int l = 0; l < NL; ++l) {
        k_msgA_mm<<<NN / 128, 256, smMA>>>(cp, msg1W, msg1b, l);
        k_edge_mm<<<NN / 128, 256, smEG>>>(inp, cp, msg1W, msg2b,
                                           upd1W, upd1b, upd2b, l);
    }
    k_out<<<NN / 128, 256, smO>>>(inp, outW1, outb1, outW2, outb2, out);
}